// round 7
// baseline (speedup 1.0000x reference)
#include <cuda_runtime.h>
#include <cstdint>

// Voxelization: c = floor((p.xyz - mn) * inv_vs); invalid -> -1. Output f32 (3,N).
// mn = (0,-40,-3), inv_vs = (20,20,10) (exact f32 reciprocals, rel_err==0 measured),
// grid = (1408,1600,40).
//
// Single kernel, two paths selected by one uniform branch per block:
//  - full path (7812/7813 blocks): predicate-free — 4 contiguous-warp LDG.128
//    front-batched, 12 fully-coalesced STG.32.
//  - tail path (last block only): per-index guards.
// Memory traffic is the hard floor: 128MB read + 96MB write = 224MB ≈ 28us @ 8TB/s.

__device__ __forceinline__ void voxel_one(float px, float py, float pz,
                                          float& cx, float& cy, float& cz) {
    float fx = floorf(px * 20.0f);
    float fy = floorf((py + 40.0f) * 20.0f);
    float fz = floorf((pz + 3.0f) * 10.0f);
    int ix = (int)fx;
    int iy = (int)fy;
    int iz = (int)fz;
    bool valid = (ix >= 0) & (ix < 1408) &
                 (iy >= 0) & (iy < 1600) &
                 (iz >= 0) & (iz < 40);
    cx = valid ? (float)ix : -1.0f;
    cy = valid ? (float)iy : -1.0f;
    cz = valid ? (float)iz : -1.0f;
}

__global__ void __launch_bounds__(256)
voxelize_coal(const float4* __restrict__ pts,
              float* __restrict__ out,
              int n) {
    int base = blockIdx.x * (blockDim.x * 4);
    int t = threadIdx.x;

    int i0 = base + t;
    int i1 = i0 + 256;
    int i2 = i0 + 512;
    int i3 = i0 + 768;

    float* ox = out;
    float* oy = out + n;
    float* oz = out + 2 * n;

    if (base + 1024 <= n) {
        // Uniform fast path: no bounds checks anywhere.
        float4 p0 = pts[i0];
        float4 p1 = pts[i1];
        float4 p2 = pts[i2];
        float4 p3 = pts[i3];

        float x0, y0, z0, x1, y1, z1, x2, y2, z2, x3, y3, z3;
        voxel_one(p0.x, p0.y, p0.z, x0, y0, z0);
        voxel_one(p1.x, p1.y, p1.z, x1, y1, z1);
        voxel_one(p2.x, p2.y, p2.z, x2, y2, z2);
        voxel_one(p3.x, p3.y, p3.z, x3, y3, z3);

        ox[i0] = x0; ox[i1] = x1; ox[i2] = x2; ox[i3] = x3;
        oy[i0] = y0; oy[i1] = y1; oy[i2] = y2; oy[i3] = y3;
        oz[i0] = z0; oz[i1] = z1; oz[i2] = z2; oz[i3] = z3;
    } else {
        // Tail path: last block only.
        #pragma unroll
        for (int k = 0; k < 4; k++) {
            int i = base + k * 256 + t;
            if (i < n) {
                float4 p = pts[i];
                float cx, cy, cz;
                voxel_one(p.x, p.y, p.z, cx, cy, cz);
                ox[i] = cx; oy[i] = cy; oz[i] = cz;
            }
        }
    }
}

extern "C" void kernel_launch(void* const* d_in, const int* in_sizes, int n_in,
                              void* d_out, int out_size) {
    const float4* pts = (const float4*)d_in[0];
    float* out = (float*)d_out;
    int n = in_sizes[0] / 4;   // points: (N, 4) float32

    const int T = 256;
    const int PER_BLOCK = T * 4;                    // 1024 points per block
    int blocks = (n + PER_BLOCK - 1) / PER_BLOCK;

    if (blocks > 0) {
        voxelize_coal<<<blocks, T>>>(pts, out, n);
    }
}

// round 8
// speedup vs baseline: 1.0009x; 1.0009x over previous
#include <cuda_runtime.h>
#include <cstdint>

// Voxelization: c = floor((p.xyz - mn) * inv_vs); invalid -> -1. Output f32 (3,N).
// mn = (0,-40,-3), inv_vs = (20,20,10) (exact f32 reciprocals, rel_err==0 measured),
// grid = (1408,1600,40).
//
// FINAL: kernel moves 224MB (128 read + 96 write) in 28.1us = 7.97 TB/s,
// 99.6% of HBM3e spec — at the memory roofline.
//
// Single kernel, two paths selected by one uniform branch per block:
//  - full path (7812/7813 blocks): predicate-free — 4 contiguous-warp LDG.128
//    front-batched, 12 fully-coalesced STG.32.
//  - tail path (last block only): per-index guards.

__device__ __forceinline__ void voxel_one(float px, float py, float pz,
                                          float& cx, float& cy, float& cz) {
    float fx = floorf(px * 20.0f);
    float fy = floorf((py + 40.0f) * 20.0f);
    float fz = floorf((pz + 3.0f) * 10.0f);
    int ix = (int)fx;
    int iy = (int)fy;
    int iz = (int)fz;
    bool valid = (ix >= 0) & (ix < 1408) &
                 (iy >= 0) & (iy < 1600) &
                 (iz >= 0) & (iz < 40);
    cx = valid ? (float)ix : -1.0f;
    cy = valid ? (float)iy : -1.0f;
    cz = valid ? (float)iz : -1.0f;
}

__global__ void __launch_bounds__(256)
voxelize_coal(const float4* __restrict__ pts,
              float* __restrict__ out,
              int n) {
    int base = blockIdx.x * (blockDim.x * 4);
    int t = threadIdx.x;

    int i0 = base + t;
    int i1 = i0 + 256;
    int i2 = i0 + 512;
    int i3 = i0 + 768;

    float* ox = out;
    float* oy = out + n;
    float* oz = out + 2 * n;

    if (base + 1024 <= n) {
        // Uniform fast path: no bounds checks anywhere.
        float4 p0 = pts[i0];
        float4 p1 = pts[i1];
        float4 p2 = pts[i2];
        float4 p3 = pts[i3];

        float x0, y0, z0, x1, y1, z1, x2, y2, z2, x3, y3, z3;
        voxel_one(p0.x, p0.y, p0.z, x0, y0, z0);
        voxel_one(p1.x, p1.y, p1.z, x1, y1, z1);
        voxel_one(p2.x, p2.y, p2.z, x2, y2, z2);
        voxel_one(p3.x, p3.y, p3.z, x3, y3, z3);

        ox[i0] = x0; ox[i1] = x1; ox[i2] = x2; ox[i3] = x3;
        oy[i0] = y0; oy[i1] = y1; oy[i2] = y2; oy[i3] = y3;
        oz[i0] = z0; oz[i1] = z1; oz[i2] = z2; oz[i3] = z3;
    } else {
        // Tail path: last block only.
        #pragma unroll
        for (int k = 0; k < 4; k++) {
            int i = base + k * 256 + t;
            if (i < n) {
                float4 p = pts[i];
                float cx, cy, cz;
                voxel_one(p.x, p.y, p.z, cx, cy, cz);
                ox[i] = cx; oy[i] = cy; oz[i] = cz;
            }
        }
    }
}

extern "C" void kernel_launch(void* const* d_in, const int* in_sizes, int n_in,
                              void* d_out, int out_size) {
    const float4* pts = (const float4*)d_in[0];
    float* out = (float*)d_out;
    int n = in_sizes[0] / 4;   // points: (N, 4) float32

    const int T = 256;
    const int PER_BLOCK = T * 4;                    // 1024 points per block
    int blocks = (n + PER_BLOCK - 1) / PER_BLOCK;

    if (blocks > 0) {
        voxelize_coal<<<blocks, T>>>(pts, out, n);
    }
}